// round 14
// baseline (speedup 1.0000x reference)
#include <cuda_runtime.h>
#include <cuda_bf16.h>

// RoIPooling: crop_and_resize bilinear, POOL 7x7.
// feature_map: [B=8, H=64, W=64, C=256] fp32
// roi_bboxes:  [B=8, N=1000, 4] fp32 (y1,x1,y2,x2) normalized
// out:         [B, N, 7, 7, C] fp32
//
// R13: R12 body (one warp per (box,py,channel-half), weight-form bilinear
// via packed fma.rn.f32x2, 4-corner LDG.128 batch, 32 regs) with ONE change:
// plain default-policy stores instead of __stcs. A/B test of the R1-era
// streaming-store assumption: default allocation lets the 126MB L2 act as a
// lazy write-combining buffer for the 401MB output stream; the 33.5MB
// feature map survives on reuse frequency (48x/pixel touch rate).

namespace {

constexpr int Hc = 64;
constexpr int Wc = 64;
constexpr int Cc = 256;          // channels
constexpr int CQ = Cc / 4;       // 64 16B-quads per pixel
constexpr int PH = 7;
constexpr int PW = 7;
constexpr int Bc = 8;
constexpr int Nc = 1000;
constexpr int NUM_WARPS = Bc * Nc * PH * 2;     // 112000 (2 channel-halves)
constexpr int WARPS_PER_BLOCK = 8;
constexpr int THREADS = WARPS_PER_BLOCK * 32;

__device__ __forceinline__ unsigned long long ffma2(
    unsigned long long a, unsigned long long b, unsigned long long c)
{
    unsigned long long d;
    asm("fma.rn.f32x2 %0, %1, %2, %3;" : "=l"(d) : "l"(a), "l"(b), "l"(c));
    return d;
}

__device__ __forceinline__ unsigned long long fmul2(
    unsigned long long a, unsigned long long b)
{
    unsigned long long d;
    asm("mul.rn.f32x2 %0, %1, %2;" : "=l"(d) : "l"(a), "l"(b));
    return d;
}

__device__ __forceinline__ unsigned long long pack2(float w)
{
    unsigned long long r;
    asm("mov.b64 %0, {%1, %1};" : "=l"(r) : "f"(w));
    return r;
}

__global__ __launch_bounds__(THREADS, 7) void roi_pool_kernel(
    const float* __restrict__ fm,
    const float* __restrict__ boxes,
    float* __restrict__ out)
{
    const int gwarp = (blockIdx.x * WARPS_PER_BLOCK) + (threadIdx.x >> 5);
    const int lane = threadIdx.x & 31;

    // gwarp = (box * PH + py) * 2 + half   (grid is exact: no bounds guard)
    const int half = gwarp & 1;
    const int row  = gwarp >> 1;       // box * PH + py
    const int py   = row % PH;
    const int box  = row / PH;         // 0 .. B*N-1 (batch-major, matches output)
    const int b    = box / Nc;

    // Box coords (16B aligned)
    const float4 bc = __ldg(reinterpret_cast<const float4*>(boxes) + box);
    const float by1 = bc.x, bx1 = bc.y, by2 = bc.z, bx2 = bc.w;

    const float hm1 = (float)(Hc - 1);
    const float wm1 = (float)(Wc - 1);

    // ---- y math: once per warp (matches reference op order) ----
    const float y = by1 * hm1 + (float)py * ((by2 - by1) * hm1 / (float)(PH - 1));
    const float y0f = floorf(y);
    const float wy  = y - y0f;
    int y0 = (int)y0f;  y0 = min(max(y0, 0), Hc - 1);
    const int y1i = min(y0 + 1, Hc - 1);
    const bool valid_y = (y >= 0.0f) & (y <= hm1);
    const float omwy = 1.0f - wy;

    // quad index within the pixel handled by this lane
    const int q = half * 32 + lane;

    // 32-bit 16B-quad offsets (fm = 8.4M quads, out = 100.4M quads < 2^31)
    const ulonglong2* fm2 = reinterpret_cast<const ulonglong2*>(fm);
    const int bbase   = b * (Hc * Wc * CQ);
    const int rowT    = bbase + y0  * (Wc * CQ) + q;   // top row, this lane's quad
    const int rowB    = bbase + y1i * (Wc * CQ) + q;   // bottom row

    // ---- x constants: once per warp ----
    const float xbase = bx1 * wm1;
    const float dx    = (bx2 - bx1) * wm1 / (float)(PW - 1);

    unsigned int oofs = (unsigned int)row * (PW * CQ) + q;
    ulonglong2* o2 = reinterpret_cast<ulonglong2*>(out);

    #pragma unroll 1
    for (int px = 0; px < PW; ++px) {
        const float x   = xbase + (float)px * dx;   // same op order as reference
        const float x0f = floorf(x);
        const float wx  = x - x0f;
        int x0 = (int)x0f;  x0 = min(max(x0, 0), Wc - 1);
        const int x1i = min(x0 + 1, Wc - 1);
        const float m = (valid_y & (x >= 0.0f) & (x <= wm1)) ? 1.0f : 0.0f;

        // Corner weights (warp-uniform per px), mask folded in; packed as
        // (w,w) f32x2 pairs. m==0 -> all weights 0 -> r == 0 exactly.
        const float omwx = 1.0f - wx;
        const unsigned long long W00 = pack2(omwx * omwy * m);  // (y0,x0)
        const unsigned long long W01 = pack2(wx   * omwy * m);  // (y0,x1)
        const unsigned long long W10 = pack2(omwx * wy   * m);  // (y1,x0)
        const unsigned long long W11 = pack2(wx   * wy   * m);  // (y1,x1)

        const int x0q = x0  * CQ;
        const int x1q = x1i * CQ;

        // Front-batch the 4 corner loads (LDG.128, MLP = 4)
        const ulonglong2 a = __ldg(fm2 + rowT + x0q);
        const ulonglong2 bq= __ldg(fm2 + rowT + x1q);
        const ulonglong2 c = __ldg(fm2 + rowB + x0q);
        const ulonglong2 d = __ldg(fm2 + rowB + x1q);

        // 8x fma.rn.f32x2 (IEEE fma per component; numerically identical
        // to the scalar fmaf chain).
        ulonglong2 r;
        r.x = ffma2(a.x, W00, ffma2(bq.x, W01, ffma2(c.x, W10, fmul2(d.x, W11))));
        r.y = ffma2(a.y, W00, ffma2(bq.y, W01, ffma2(c.y, W10, fmul2(d.y, W11))));

        // Plain default-policy store (A/B vs __stcs): let L2 write-combine
        // the output stream lazily; fm lines survive on reuse frequency.
        o2[oofs] = r;
        oofs += CQ;
    }
}

} // namespace

extern "C" void kernel_launch(void* const* d_in, const int* in_sizes, int n_in,
                              void* d_out, int out_size) {
    const float* fm    = (const float*)d_in[0];
    const float* boxes = (const float*)d_in[1];
    float* out         = (float*)d_out;

    const int blocks = NUM_WARPS / WARPS_PER_BLOCK;  // 14000, exact
    roi_pool_kernel<<<blocks, THREADS>>>(fm, boxes, out);
}

// round 15
// speedup vs baseline: 1.0631x; 1.0631x over previous
#include <cuda_runtime.h>
#include <cuda_bf16.h>

// RoIPooling: crop_and_resize bilinear, POOL 7x7.
// feature_map: [B=8, H=64, W=64, C=256] fp32
// roi_bboxes:  [B=8, N=1000, 4] fp32 (y1,x1,y2,x2) normalized
// out:         [B, N, 7, 7, C] fp32
//
// FINAL (R12 configuration, re-locked after the R13 store-policy A/B):
//  - one warp per (box, py, channel-half): 112000 warps, 32 regs, ~90% occ
//  - weight-form bilinear with validity folded into the 4 corner weights
//  - packed fma.rn.f32x2 (8 FFMA2 instead of 16 FFMA per iteration)
//  - 4-corner LDG.128 front-batch (MLP=4), 32-bit offset arithmetic
//  - __stcs streaming stores (A/B-proven: default stores cost +6us by
//    letting the 401MB output stream pollute L2 and slow writeback drain)
// Plateau analysis: LSU-port bound at ~67% of the 59us wavefront floor;
// R4/R5/R6/R8/R9/R10/R11/R13 structural variants all regressed or tied.

namespace {

constexpr int Hc = 64;
constexpr int Wc = 64;
constexpr int Cc = 256;          // channels
constexpr int CQ = Cc / 4;       // 64 16B-quads per pixel
constexpr int PH = 7;
constexpr int PW = 7;
constexpr int Bc = 8;
constexpr int Nc = 1000;
constexpr int NUM_WARPS = Bc * Nc * PH * 2;     // 112000 (2 channel-halves)
constexpr int WARPS_PER_BLOCK = 8;
constexpr int THREADS = WARPS_PER_BLOCK * 32;

__device__ __forceinline__ unsigned long long ffma2(
    unsigned long long a, unsigned long long b, unsigned long long c)
{
    unsigned long long d;
    asm("fma.rn.f32x2 %0, %1, %2, %3;" : "=l"(d) : "l"(a), "l"(b), "l"(c));
    return d;
}

__device__ __forceinline__ unsigned long long fmul2(
    unsigned long long a, unsigned long long b)
{
    unsigned long long d;
    asm("mul.rn.f32x2 %0, %1, %2;" : "=l"(d) : "l"(a), "l"(b));
    return d;
}

__device__ __forceinline__ unsigned long long pack2(float w)
{
    unsigned long long r;
    asm("mov.b64 %0, {%1, %1};" : "=l"(r) : "f"(w));
    return r;
}

__global__ __launch_bounds__(THREADS, 7) void roi_pool_kernel(
    const float* __restrict__ fm,
    const float* __restrict__ boxes,
    float* __restrict__ out)
{
    const int gwarp = (blockIdx.x * WARPS_PER_BLOCK) + (threadIdx.x >> 5);
    const int lane = threadIdx.x & 31;

    // gwarp = (box * PH + py) * 2 + half   (grid is exact: no bounds guard)
    const int half = gwarp & 1;
    const int row  = gwarp >> 1;       // box * PH + py
    const int py   = row % PH;
    const int box  = row / PH;         // 0 .. B*N-1 (batch-major, matches output)
    const int b    = box / Nc;

    // Box coords (16B aligned)
    const float4 bc = __ldg(reinterpret_cast<const float4*>(boxes) + box);
    const float by1 = bc.x, bx1 = bc.y, by2 = bc.z, bx2 = bc.w;

    const float hm1 = (float)(Hc - 1);
    const float wm1 = (float)(Wc - 1);

    // ---- y math: once per warp (matches reference op order) ----
    const float y = by1 * hm1 + (float)py * ((by2 - by1) * hm1 / (float)(PH - 1));
    const float y0f = floorf(y);
    const float wy  = y - y0f;
    int y0 = (int)y0f;  y0 = min(max(y0, 0), Hc - 1);
    const int y1i = min(y0 + 1, Hc - 1);
    const bool valid_y = (y >= 0.0f) & (y <= hm1);
    const float omwy = 1.0f - wy;

    // quad index within the pixel handled by this lane
    const int q = half * 32 + lane;

    // 32-bit 16B-quad offsets (fm = 8.4M quads, out = 100.4M quads < 2^31)
    const ulonglong2* fm2 = reinterpret_cast<const ulonglong2*>(fm);
    const int bbase   = b * (Hc * Wc * CQ);
    const int rowT    = bbase + y0  * (Wc * CQ) + q;   // top row, this lane's quad
    const int rowB    = bbase + y1i * (Wc * CQ) + q;   // bottom row

    // ---- x constants: once per warp ----
    const float xbase = bx1 * wm1;
    const float dx    = (bx2 - bx1) * wm1 / (float)(PW - 1);

    unsigned int oofs = (unsigned int)row * (PW * CQ) + q;
    ulonglong2* o2 = reinterpret_cast<ulonglong2*>(out);

    #pragma unroll 1
    for (int px = 0; px < PW; ++px) {
        const float x   = xbase + (float)px * dx;   // same op order as reference
        const float x0f = floorf(x);
        const float wx  = x - x0f;
        int x0 = (int)x0f;  x0 = min(max(x0, 0), Wc - 1);
        const int x1i = min(x0 + 1, Wc - 1);
        const float m = (valid_y & (x >= 0.0f) & (x <= wm1)) ? 1.0f : 0.0f;

        // Corner weights (warp-uniform per px), mask folded in; packed as
        // (w,w) f32x2 pairs. m==0 -> all weights 0 -> r == 0 exactly.
        const float omwx = 1.0f - wx;
        const unsigned long long W00 = pack2(omwx * omwy * m);  // (y0,x0)
        const unsigned long long W01 = pack2(wx   * omwy * m);  // (y0,x1)
        const unsigned long long W10 = pack2(omwx * wy   * m);  // (y1,x0)
        const unsigned long long W11 = pack2(wx   * wy   * m);  // (y1,x1)

        const int x0q = x0  * CQ;
        const int x1q = x1i * CQ;

        // Front-batch the 4 corner loads (LDG.128, MLP = 4)
        const ulonglong2 a = __ldg(fm2 + rowT + x0q);
        const ulonglong2 bq= __ldg(fm2 + rowT + x1q);
        const ulonglong2 c = __ldg(fm2 + rowB + x0q);
        const ulonglong2 d = __ldg(fm2 + rowB + x1q);

        // 8x fma.rn.f32x2 (IEEE fma per component; numerically identical
        // to the scalar fmaf chain).
        ulonglong2 r;
        r.x = ffma2(a.x, W00, ffma2(bq.x, W01, ffma2(c.x, W10, fmul2(d.x, W11))));
        r.y = ffma2(a.y, W00, ffma2(bq.y, W01, ffma2(c.y, W10, fmul2(d.y, W11))));

        // Streaming store (A/B-proven): keep the 401MB output stream from
        // evicting the 33.5MB feature map out of L2.
        __stcs(reinterpret_cast<ulonglong2*>(o2 + oofs), r);
        oofs += CQ;
    }
}

} // namespace

extern "C" void kernel_launch(void* const* d_in, const int* in_sizes, int n_in,
                              void* d_out, int out_size) {
    const float* fm    = (const float*)d_in[0];
    const float* boxes = (const float*)d_in[1];
    float* out         = (float*)d_out;

    const int blocks = NUM_WARPS / WARPS_PER_BLOCK;  // 14000, exact
    roi_pool_kernel<<<blocks, THREADS>>>(fm, boxes, out);
}